// round 15
// baseline (speedup 1.0000x reference)
#include <cuda_runtime.h>
#include <cuda_bf16.h>
#include <math.h>
#include <stdint.h>

#define NN 50000
#define EE 100000
#define HH 64
#define GG 64
#define OUTD 32

// ---------------- device scratch (static globals; no runtime allocation) ---------------
__device__ float g_h[(size_t)NN * HH];          // node state
__device__ float g_magg[(size_t)NN * HH];       // aggregated messages
__device__ float g_b2p[4096];                   // column-permuted b_e2
__device__ float g_gsum[GG * HH];               // per-graph sums
// ew in bf16 pairs: g_ewb[e][j][i/2] = (ew[e,i,j], ew[e,i+1,j])
__device__ __nv_bfloat162 g_ewb[(size_t)EE * 2048];
// bf16-split, permuted+transposed W_e2: rows q (0..4095), cols k (0..63)
__device__ __nv_bfloat16 g_W2Thi[(size_t)4096 * 64];
__device__ __nv_bfloat16 g_W2Tlo[(size_t)4096 * 64];
// bf16-split edge hidden t: [e][k]
__device__ __nv_bfloat16 g_thi[(size_t)EE * 64];
__device__ __nv_bfloat16 g_tlo[(size_t)EE * 64];
// GRU fused gate weights, bf16-split, [n=256 outputs][k'=128 (m|h)] k-contiguous.
// cols n: [0,64)=r-sum  [64,128)=z-sum  [128,192)=gin (h-part 0)  [192,256)=ghn (m-part 0)
__device__ __nv_bfloat16 g_Bhi[256 * 128];
__device__ __nv_bfloat16 g_Blo[256 * 128];

// ---------------- small helpers ----------------
__device__ __forceinline__ float sigm(float x) { return 1.0f / (1.0f + expf(-x)); }

__device__ __forceinline__ uint32_t smem_u32(const void* p) {
    uint32_t a;
    asm("{ .reg .u64 t; cvta.to.shared.u64 t, %1; cvt.u32.u64 %0, t; }" : "=r"(a) : "l"(p));
    return a;
}

// ---------------- node encoder (self-contained): h = x@W_enc + b, magg = 0 ----------
__global__ void __launch_bounds__(256) enc_kernel(const float* __restrict__ x,
                                                  const float* __restrict__ Wenc,
                                                  const float* __restrict__ benc) {
    __shared__ float sx[16][128];
    int n0 = blockIdx.x * 16;
    int tid = threadIdx.x;
#pragma unroll
    for (int i = 0; i < 2; i++) {
        int f = i * 256 + tid;
        int row = f >> 5, q4 = (f & 31) * 4;
        *(float4*)&sx[row][q4] = *(const float4*)&x[(size_t)(n0 + row) * 128 + q4];
    }
    __syncthreads();
    int slot = tid >> 6, c = tid & 63;
    float b = benc[c];
    float acc[4] = {b, b, b, b};
    const float* xr = &sx[slot * 4][0];
#pragma unroll 8
    for (int k = 0; k < 128; k++) {
        float w = Wenc[k * 64 + c];
#pragma unroll
        for (int u = 0; u < 4; u++)
            acc[u] = fmaf(xr[u * 128 + k], w, acc[u]);
    }
#pragma unroll
    for (int u = 0; u < 4; u++) {
        int n = n0 + slot * 4 + u;
        g_h[(size_t)n * 64 + c] = acc[u];
        g_magg[(size_t)n * 64 + c] = 0.0f;
    }
}

// ---------------- edge_prep: edge_t + splitW2 + GRU B-pack (grid-branched) ----------
// blocks [0,25000): t = relu(ea@W_e1+b_e1) -> bf16 hi/lo  (4 edges per block)
// blocks [25000,26024): bf16 hi/lo split of permuted-transposed W_e2
// blocks [26024,26152): GRU fused gate weight pack (g_Bhi/g_Blo)
__global__ void __launch_bounds__(256) edge_prep_kernel(
    const float* __restrict__ ea, const float* __restrict__ be1,
    const float* __restrict__ W1,
    const float* __restrict__ W2, const float* __restrict__ b2,
    const float* __restrict__ Wih, const float* __restrict__ Whh) {
    int b = blockIdx.x;
    int tid = threadIdx.x;
    if (b < 25000) {
        __shared__ float sW1[1024];
        __shared__ float sea[4][16];
        __shared__ float sbe[64];
        int e0 = b * 4;
#pragma unroll
        for (int i = 0; i < 4; i++) sW1[i * 256 + tid] = W1[i * 256 + tid];
        if (tid < 64) {
            sea[tid >> 4][tid & 15] = ea[(size_t)e0 * 16 + tid];
            sbe[tid] = be1[tid];
        }
        __syncthreads();
        int le = tid >> 6, c = tid & 63;
        int e = e0 + le;
        float acc = sbe[c];
#pragma unroll
        for (int k = 0; k < 16; k++)
            acc = fmaf(sea[le][k], sW1[k * 64 + c], acc);
        float v = fmaxf(acc, 0.0f);
        __nv_bfloat16 hi = __float2bfloat16(v);
        size_t idx = (size_t)e * 64 + c;
        g_thi[idx] = hi;
        g_tlo[idx] = __float2bfloat16(v - __bfloat162float(hi));
    } else if (b < 26024) {
        int idx = (b - 25000) * 256 + tid;
        int q = idx >> 6, k = idx & 63;
        int i = q & 63, j = q >> 6;
        float v = W2[(size_t)k * 4096 + i * 64 + j];
        __nv_bfloat16 hi = __float2bfloat16(v);
        g_W2Thi[idx] = hi;
        g_W2Tlo[idx] = __float2bfloat16(v - __bfloat162float(hi));
        if (k == 0) g_b2p[q] = b2[i * 64 + j];
    } else {
        int idx = (b - 26024) * 256 + tid;     // 0..32767
        int n = idx >> 7, k = idx & 127;
        float v;
        if (n < 128) {
            // r-sum / z-sum columns: Wih row n on m-part, Whh row n on h-part
            v = (k < 64) ? Wih[(size_t)n * 64 + k] : Whh[(size_t)n * 64 + (k - 64)];
        } else if (n < 192) {
            // gin: Wih row n (128..191) on m-part only
            v = (k < 64) ? Wih[(size_t)n * 64 + k] : 0.0f;
        } else {
            // ghn: Whh row n-64 (128..191) on h-part only
            v = (k < 64) ? 0.0f : Whh[(size_t)(n - 64) * 64 + (k - 64)];
        }
        __nv_bfloat16 hi = __float2bfloat16(v);
        g_Bhi[idx] = hi;
        g_Blo[idx] = __float2bfloat16(v - __bfloat162float(hi));
    }
}

// ---------------- ew GEMM via mma.sync (bf16 split, dedup'd smem) ----------------
// CTA: 128e x 128q, 4 warps of 64x64. smem rows hold [hi(64) | lo(64)] (no dup)
// -> 70 KB smem -> 3 CTAs/SM. 12 k-steps select (A,B) segment by byte offset.
#define AROW 272   // bytes per smem row: 128 bf16 + 16B pad (odd 16B multiple)

__global__ void __launch_bounds__(128, 3) ew_gemm_mma_kernel() {
    extern __shared__ __nv_bfloat16 dsm[];
    char* sA = (char*)dsm;                   // 128 x AROW
    char* sB = (char*)dsm + 128 * AROW;      // 128 x AROW
    __shared__ float sbias[128];

    int tid = threadIdx.x;
    int q0 = blockIdx.x * 128;
    int e0 = blockIdx.y * 128;

    sbias[tid] = g_b2p[q0 + tid];

    // load A and B tiles: seg 0 = hi at byte 0, seg 1 = lo at byte 128
#pragma unroll
    for (int seg = 0; seg < 2; seg++) {
        const __nv_bfloat16* asrc = seg ? g_tlo : g_thi;
        const __nv_bfloat16* bsrc = seg ? g_W2Tlo : g_W2Thi;
        int soff = seg * 128;
#pragma unroll
        for (int i = 0; i < 8; i++) {
            int flat = i * 128 + tid;        // 0..1023
            int row = flat >> 3, u = flat & 7;
            int e = e0 + row;
            uint4 av = make_uint4(0u, 0u, 0u, 0u);
            if (e < EE) av = *(const uint4*)&asrc[(size_t)e * 64 + u * 8];
            *(uint4*)(sA + row * AROW + soff + u * 16) = av;
            uint4 bv = *(const uint4*)&bsrc[(size_t)(q0 + row) * 64 + u * 8];
            *(uint4*)(sB + row * AROW + soff + u * 16) = bv;
        }
    }
    __syncthreads();

    int warp = tid >> 5, lane = tid & 31;
    int wm = (warp & 1) * 64;
    int wn = (warp >> 1) * 64;

    float acc[4][8][4];
#pragma unroll
    for (int a = 0; a < 4; a++)
#pragma unroll
        for (int b = 0; b < 8; b++)
#pragma unroll
            for (int c = 0; c < 4; c++) acc[a][b][c] = 0.0f;

    uint32_t sA32 = smem_u32(sA);
    uint32_t sB32 = smem_u32(sB);

    int alr = ((lane >> 3) & 1) * 8 + (lane & 7);
    int alc = (lane >> 4) * 8;
    uint32_t aBase = sA32 + (wm + alr) * AROW + alc * 2;

    int bg = lane >> 3;
    int blr = ((bg >> 1) * 8) + (lane & 7);
    int blc = (bg & 1) * 8;
    uint32_t bBase = sB32 + (wn + blr) * AROW + blc * 2;

#pragma unroll
    for (int ks = 0; ks < 12; ks++) {
        int seg = ks >> 2;                       // 0: hh, 1: hl, 2: lh
        uint32_t aoff = ((seg == 2) ? 128u : 0u) + (ks & 3) * 32;
        uint32_t boff = ((seg == 1) ? 128u : 0u) + (ks & 3) * 32;
        uint32_t a[4][4], bf[4][4];
#pragma unroll
        for (int mt = 0; mt < 4; mt++) {
            asm volatile("ldmatrix.sync.aligned.m8n8.x4.shared.b16 {%0,%1,%2,%3}, [%4];"
                         : "=r"(a[mt][0]), "=r"(a[mt][1]), "=r"(a[mt][2]), "=r"(a[mt][3])
                         : "r"(aBase + mt * 16 * AROW + aoff));
        }
#pragma unroll
        for (int g = 0; g < 4; g++) {
            asm volatile("ldmatrix.sync.aligned.m8n8.x4.shared.b16 {%0,%1,%2,%3}, [%4];"
                         : "=r"(bf[g][0]), "=r"(bf[g][1]), "=r"(bf[g][2]), "=r"(bf[g][3])
                         : "r"(bBase + g * 16 * AROW + boff));
        }
#pragma unroll
        for (int mt = 0; mt < 4; mt++) {
#pragma unroll
            for (int g = 0; g < 4; g++) {
#pragma unroll
                for (int h = 0; h < 2; h++) {
                    int nt = g * 2 + h;
                    asm volatile(
                        "mma.sync.aligned.m16n8k16.row.col.f32.bf16.bf16.f32 "
                        "{%0,%1,%2,%3}, {%4,%5,%6,%7}, {%8,%9}, {%0,%1,%2,%3};"
                        : "+f"(acc[mt][nt][0]), "+f"(acc[mt][nt][1]),
                          "+f"(acc[mt][nt][2]), "+f"(acc[mt][nt][3])
                        : "r"(a[mt][0]), "r"(a[mt][1]), "r"(a[mt][2]), "r"(a[mt][3]),
                          "r"(bf[g][h * 2]), "r"(bf[g][h * 2 + 1]));
                }
            }
        }
    }

    // epilogue: add bias, convert to bf16 pair (i, i+1), store 4B per element-pair
#pragma unroll
    for (int mt = 0; mt < 4; mt++) {
        int er0 = e0 + wm + mt * 16 + (lane >> 2);
        int er1 = er0 + 8;
#pragma unroll
        for (int nt = 0; nt < 8; nt++) {
            int qrel = wn + nt * 8 + (lane & 3) * 2;
            float bx = sbias[qrel], by = sbias[qrel + 1];
            int q = q0 + qrel;
            int j = q >> 6, ip = (q & 63) >> 1;
            size_t off = (size_t)j * 32 + ip;
            if (er0 < EE) {
                __nv_bfloat162 v;
                v.x = __float2bfloat16(acc[mt][nt][0] + bx);
                v.y = __float2bfloat16(acc[mt][nt][1] + by);
                g_ewb[(size_t)er0 * 2048 + off] = v;
            }
            if (er1 < EE) {
                __nv_bfloat162 v;
                v.x = __float2bfloat16(acc[mt][nt][2] + bx);
                v.y = __float2bfloat16(acc[mt][nt][3] + by);
                g_ewb[(size_t)er1 * 2048 + off] = v;
            }
        }
    }
}

// ---------------- zero kernel ----------------
__global__ void zero_gsum_kernel() {
    int i = blockIdx.x * blockDim.x + threadIdx.x;
    if (i < GG * 64) g_gsum[i] = 0.0f;
}

// ---------------- per-edge matvec + scatter: 1 warp per edge, bf16 pairs -------------
__global__ void msg_kernel(const int* __restrict__ ei) {
    __shared__ float hs[8][64];
    int w = threadIdx.x >> 5, lane = threadIdx.x & 31;
    int e = blockIdx.x * 8 + w;
    int s = ei[e];
    hs[w][lane]      = g_h[(size_t)s * 64 + lane];
    hs[w][lane + 32] = g_h[(size_t)s * 64 + 32 + lane];
    __syncwarp();
    const __nv_bfloat162* row = &g_ewb[(size_t)e * 2048 + lane];
    const float* hb = hs[w];
    float acc0 = 0.0f, acc1 = 0.0f;
#pragma unroll
    for (int j = 0; j < 64; j++) {
        __nv_bfloat162 v = __ldcs(&row[(size_t)j * 32]);
        float hj = hb[j];
        acc0 = fmaf(__bfloat162float(v.x), hj, acc0);
        acc1 = fmaf(__bfloat162float(v.y), hj, acc1);
    }
    int d = ei[EE + e];
    float* dst = &g_magg[(size_t)d * 64 + 2 * lane];
    atomicAdd(dst, acc0);
    atomicAdd(dst + 1, acc1);
}

// ---------------- GRU via tensor cores -------------------------------------------
// Per 64-node tile: C[64,256] = [m|h] (K'=128, bf16-split x3) @ B'.
// cols: [0,64)=r-sum  [64,128)=z-sum  [128,192)=gin  [192,256)=ghn.
// A in smem (hi+lo), B fragments LDG'd from L2-resident g_Bhi/g_Blo.
// Epilogue: exchange via smem, apply gates, write h, re-zero magg.
#define GAROW 272                   // A smem row: 128 bf16 + 16B pad
#define GSM_A_HI 0
#define GSM_A_LO (64 * GAROW)       // 17408
#define GSM_TOTAL (64 * 258 * 4)    // C exchange: 64 x 258 floats = 66048 (union w/ A)

__global__ void __launch_bounds__(256, 3) gru_mma_kernel(const float* __restrict__ bih,
                                                         const float* __restrict__ bhh) {
    extern __shared__ char gsm[];
    int tid = threadIdx.x;
    int n0 = blockIdx.x * 64;
    int warp = tid >> 5, lane = tid & 31;

    // ---- build A (hi/lo) in smem: row r = node, cols k'<64 = magg, k'>=64 = h ----
    {
        int r = tid >> 2;                    // 0..63
        int kq = (tid & 3) * 32;             // 0,32,64,96
        int n = n0 + r;
        __nv_bfloat16* ahi = (__nv_bfloat16*)(gsm + GSM_A_HI + r * GAROW) + kq;
        __nv_bfloat16* alo = (__nv_bfloat16*)(gsm + GSM_A_LO + r * GAROW) + kq;
        const float* src = (kq < 64) ? &g_magg[(size_t)n * 64 + kq]
                                     : &g_h[(size_t)n * 64 + (kq - 64)];
#pragma unroll
        for (int u = 0; u < 8; u++) {
            float4 v = make_float4(0.f, 0.f, 0.f, 0.f);
            if (n < NN) v = *(const float4*)&src[u * 4];
            float vv[4] = {v.x, v.y, v.z, v.w};
#pragma unroll
            for (int p = 0; p < 4; p++) {
                __nv_bfloat16 hi = __float2bfloat16(vv[p]);
                ahi[u * 4 + p] = hi;
                alo[u * 4 + p] = __float2bfloat16(vv[p] - __bfloat162float(hi));
            }
        }
    }
    __syncthreads();

    // ---- mma: warp tile 32 nodes x 64 cols; warps: 2m x 4n ----
    int wm = (warp & 1) * 32;
    int wn = (warp >> 1) * 64;
    float acc[2][8][4];
#pragma unroll
    for (int a = 0; a < 2; a++)
#pragma unroll
        for (int b = 0; b < 8; b++)
#pragma unroll
            for (int c = 0; c < 4; c++) acc[a][b][c] = 0.0f;

    uint32_t sA32 = smem_u32(gsm);
    int alr = ((lane >> 3) & 1) * 8 + (lane & 7);
    int alc = (lane >> 4) * 8;
    uint32_t aBase = sA32 + (wm + alr) * GAROW + alc * 2;

    int bn = lane >> 2;                     // n offset within n8-group? no: 0..7
    int bk2 = (lane & 3) * 2;               // k pair offset

#pragma unroll
    for (int pass = 0; pass < 3; pass++) {
        uint32_t aoff = (pass == 2) ? (uint32_t)GSM_A_LO : 0u;
        const __nv_bfloat16* Bp = (pass == 1) ? g_Blo : g_Bhi;
#pragma unroll
        for (int ks = 0; ks < 8; ks++) {
            int k0 = ks * 16;
            uint32_t a[2][4];
#pragma unroll
            for (int mt = 0; mt < 2; mt++) {
                asm volatile("ldmatrix.sync.aligned.m8n8.x4.shared.b16 {%0,%1,%2,%3}, [%4];"
                             : "=r"(a[mt][0]), "=r"(a[mt][1]), "=r"(a[mt][2]), "=r"(a[mt][3])
                             : "r"(aBase + aoff + mt * 16 * GAROW + k0 * 2));
            }
#pragma unroll
            for (int nt = 0; nt < 8; nt++) {
                int n = wn + nt * 8 + bn;
                const uint32_t* bp = (const uint32_t*)&Bp[(size_t)n * 128 + k0 + bk2];
                uint32_t b0 = bp[0];
                uint32_t b1 = bp[4];         // +8 bf16 = +4 uint32
#pragma unroll
                for (int mt = 0; mt < 2; mt++) {
                    asm volatile(
                        "mma.sync.aligned.m16n8k16.row.col.f32.bf16.bf16.f32 "
                        "{%0,%1,%2,%3}, {%4,%5,%6,%7}, {%8,%9}, {%0,%1,%2,%3};"
                        : "+f"(acc[mt][nt][0]), "+f"(acc[mt][nt][1]),
                          "+f"(acc[mt][nt][2]), "+f"(acc[mt][nt][3])
                        : "r"(a[mt][0]), "r"(a[mt][1]), "r"(a[mt][2]), "r"(a[mt][3]),
                          "r"(b0), "r"(b1));
                }
            }
        }
    }
    __syncthreads();   // A reads done; reuse smem as C exchange

    // ---- write C to smem [64][258] floats ----
    float* Cf = (float*)gsm;
#pragma unroll
    for (int mt = 0; mt < 2; mt++) {
        int r0 = wm + mt * 16 + (lane >> 2);
        int r1 = r0 + 8;
#pragma unroll
        for (int nt = 0; nt < 8; nt++) {
            int col = wn + nt * 8 + (lane & 3) * 2;
            *(float2*)&Cf[r0 * 258 + col] = make_float2(acc[mt][nt][0], acc[mt][nt][1]);
            *(float2*)&Cf[r1 * 258 + col] = make_float2(acc[mt][nt][2], acc[mt][nt][3]);
        }
    }
    __syncthreads();

    // ---- gates + state update: 16 outputs per thread ----
    {
        int c = tid & 63;
        float br = bih[c] + bhh[c];
        float bz = bih[64 + c] + bhh[64 + c];
        float bi_n = bih[128 + c];
        float bh_n = bhh[128 + c];
#pragma unroll
        for (int i = 0; i < 16; i++) {
            int f = i * 256 + tid;
            int nloc = f >> 6;               // 0..63
            int n = n0 + nloc;
            if (n < NN) {
                float Cr = Cf[nloc * 258 + c];
                float Cz = Cf[nloc * 258 + 64 + c];
                float Ci = Cf[nloc * 258 + 128 + c];
                float Ch = Cf[nloc * 258 + 192 + c];
                float r = sigm(Cr + br);
                float z = sigm(Cz + bz);
                float nv = tanhf(Ci + bi_n + r * (Ch + bh_n));
                float hold = g_h[(size_t)n * 64 + c];
                g_h[(size_t)n * 64 + c] = (1.0f - z) * nv + z * hold;
                g_magg[(size_t)n * 64 + c] = 0.0f;
            }
        }
    }
}

// ---------------- graph readout scatter ----------------
__global__ void rsum_kernel(const int* __restrict__ batch) {
    int idx = blockIdx.x * blockDim.x + threadIdx.x;
    if (idx >= NN * 64) return;
    int n = idx >> 6, c = idx & 63;
    atomicAdd(&g_gsum[batch[n] * 64 + c], g_h[idx]);
}

// ---------------- final MLP: relu(g@W_r1+b_r1)@W_r2+b_r2 ----------------
__global__ void final_kernel(const float* __restrict__ Wr1, const float* __restrict__ br1,
                             const float* __restrict__ Wr2, const float* __restrict__ br2,
                             float* __restrict__ out) {
    __shared__ float sg[64], sr[64];
    int g = blockIdx.x;
    int c = threadIdx.x;
    sg[c] = g_gsum[g * 64 + c];
    __syncthreads();
    float acc = br1[c];
#pragma unroll
    for (int k = 0; k < 64; k++) acc = fmaf(sg[k], Wr1[k * 64 + c], acc);
    sr[c] = fmaxf(acc, 0.0f);
    __syncthreads();
    if (c < OUTD) {
        float o = br2[c];
#pragma unroll
        for (int k = 0; k < 64; k++) o = fmaf(sr[k], Wr2[k * 32 + c], o);
        out[g * OUTD + c] = o;
    }
}

// ---------------- launch ----------------
extern "C" void kernel_launch(void* const* d_in, const int* in_sizes, int n_in,
                              void* d_out, int out_size) {
    const float* x    = (const float*)d_in[0];
    const int*   ei   = (const int*)d_in[1];
    const float* ea   = (const float*)d_in[2];
    const int*   batch= (const int*)d_in[3];
    const float* Wenc = (const float*)d_in[4];
    const float* benc = (const float*)d_in[5];
    const float* We1  = (const float*)d_in[6];
    const float* be1  = (const float*)d_in[7];
    const float* We2  = (const float*)d_in[8];
    const float* be2  = (const float*)d_in[9];
    const float* Wih  = (const float*)d_in[10];
    const float* Whh  = (const float*)d_in[11];
    const float* bih  = (const float*)d_in[12];
    const float* bhh  = (const float*)d_in[13];
    const float* Wr1  = (const float*)d_in[14];
    const float* br1  = (const float*)d_in[15];
    const float* Wr2  = (const float*)d_in[16];
    const float* br2  = (const float*)d_in[17];
    float* out = (float*)d_out;

    const int gemm_smem = 2 * 128 * AROW;        // 69632
    cudaFuncSetAttribute(ew_gemm_mma_kernel,
                         cudaFuncAttributeMaxDynamicSharedMemorySize, gemm_smem);
    cudaFuncSetAttribute(gru_mma_kernel,
                         cudaFuncAttributeMaxDynamicSharedMemorySize, GSM_TOTAL);

    // Slot order: enc(1), edge_prep(2), zero_gsum(3), gemm(4) <- ncu captures #4.
    enc_kernel<<<NN / 16, 256>>>(x, Wenc, benc);
    edge_prep_kernel<<<25000 + 1024 + 128, 256>>>(ea, be1, We1, We2, be2, Wih, Whh);
    zero_gsum_kernel<<<16, 256>>>();
    ew_gemm_mma_kernel<<<dim3(32, (EE + 127) / 128), 128, gemm_smem>>>();

    for (int s = 0; s < 3; s++) {
        msg_kernel<<<EE / 8, 256>>>(ei);
        gru_mma_kernel<<<(NN + 63) / 64, 256, GSM_TOTAL>>>(bih, bhh);
    }

    rsum_kernel<<<(NN * 64 + 255) / 256, 256>>>(batch);
    final_kernel<<<GG, 64>>>(Wr1, br1, Wr2, br2, out);
}

// round 16
// speedup vs baseline: 1.4971x; 1.4971x over previous
#include <cuda_runtime.h>
#include <cuda_bf16.h>
#include <math.h>
#include <stdint.h>

#define NN 50000
#define EE 100000
#define HH 64
#define GG 64
#define OUTD 32

// ---------------- device scratch (static globals; no runtime allocation) ---------------
__device__ float g_h[(size_t)NN * HH];          // node state
__device__ float g_magg[(size_t)NN * HH];       // aggregated messages
__device__ float g_b2p[4096];                   // column-permuted b_e2
__device__ float g_WihT[64 * 192];              // GRU input weights transposed [k][3H]
__device__ float g_WhhT[64 * 192];              // GRU hidden weights transposed [k][3H]
__device__ float g_gsum[GG * HH];               // per-graph sums
// ew in bf16 pairs: g_ewb[e][j][i/2] = (ew[e,i,j], ew[e,i+1,j])
__device__ __nv_bfloat162 g_ewb[(size_t)EE * 2048];
// bf16-split, permuted+transposed W_e2: rows q (0..4095), cols k (0..63)
__device__ __nv_bfloat16 g_W2Thi[(size_t)4096 * 64];
__device__ __nv_bfloat16 g_W2Tlo[(size_t)4096 * 64];
// bf16-split edge hidden t: [e][k]
__device__ __nv_bfloat16 g_thi[(size_t)EE * 64];
__device__ __nv_bfloat16 g_tlo[(size_t)EE * 64];

// ---------------- small helpers ----------------
__device__ __forceinline__ float sigm(float x) { return 1.0f / (1.0f + expf(-x)); }

__device__ __forceinline__ uint32_t smem_u32(const void* p) {
    uint32_t a;
    asm("{ .reg .u64 t; cvta.to.shared.u64 t, %1; cvt.u32.u64 %0, t; }" : "=r"(a) : "l"(p));
    return a;
}

__device__ __forceinline__ uint32_t pack_bf2(float a, float b) {
    __nv_bfloat162 t;
    t.x = __float2bfloat16(a);
    t.y = __float2bfloat16(b);
    return *(uint32_t*)&t;
}

// ---------------- node encoder (self-contained): h = x@W_enc + b, magg = 0 ----------
__global__ void __launch_bounds__(256) enc_kernel(const float* __restrict__ x,
                                                  const float* __restrict__ Wenc,
                                                  const float* __restrict__ benc) {
    __shared__ float sx[16][128];
    int n0 = blockIdx.x * 16;
    int tid = threadIdx.x;
#pragma unroll
    for (int i = 0; i < 2; i++) {
        int f = i * 256 + tid;
        int row = f >> 5, q4 = (f & 31) * 4;
        *(float4*)&sx[row][q4] = *(const float4*)&x[(size_t)(n0 + row) * 128 + q4];
    }
    __syncthreads();
    int slot = tid >> 6, c = tid & 63;
    float b = benc[c];
    float acc[4] = {b, b, b, b};
    const float* xr = &sx[slot * 4][0];
#pragma unroll 8
    for (int k = 0; k < 128; k++) {
        float w = Wenc[k * 64 + c];
#pragma unroll
        for (int u = 0; u < 4; u++)
            acc[u] = fmaf(xr[u * 128 + k], w, acc[u]);
    }
#pragma unroll
    for (int u = 0; u < 4; u++) {
        int n = n0 + slot * 4 + u;
        g_h[(size_t)n * 64 + c] = acc[u];
        g_magg[(size_t)n * 64 + c] = 0.0f;
    }
}

// ---------------- edge_prep: edge_t + splitW2 + GRU weight transpose (grid-branched) --
__global__ void __launch_bounds__(256) edge_prep_kernel(
    const float* __restrict__ ea, const float* __restrict__ be1,
    const float* __restrict__ W1,
    const float* __restrict__ W2, const float* __restrict__ b2,
    const float* __restrict__ Wih, const float* __restrict__ Whh) {
    int b = blockIdx.x;
    int tid = threadIdx.x;
    if (b < 25000) {
        __shared__ float sW1[1024];
        __shared__ float sea[4][16];
        __shared__ float sbe[64];
        int e0 = b * 4;
#pragma unroll
        for (int i = 0; i < 4; i++) sW1[i * 256 + tid] = W1[i * 256 + tid];
        if (tid < 64) {
            sea[tid >> 4][tid & 15] = ea[(size_t)e0 * 16 + tid];
            sbe[tid] = be1[tid];
        }
        __syncthreads();
        int le = tid >> 6, c = tid & 63;
        int e = e0 + le;
        float acc = sbe[c];
#pragma unroll
        for (int k = 0; k < 16; k++)
            acc = fmaf(sea[le][k], sW1[k * 64 + c], acc);
        float v = fmaxf(acc, 0.0f);
        __nv_bfloat16 hi = __float2bfloat16(v);
        size_t idx = (size_t)e * 64 + c;
        g_thi[idx] = hi;
        g_tlo[idx] = __float2bfloat16(v - __bfloat162float(hi));
    } else if (b < 26024) {
        int idx = (b - 25000) * 256 + tid;
        int q = idx >> 6, k = idx & 63;
        int i = q & 63, j = q >> 6;
        float v = W2[(size_t)k * 4096 + i * 64 + j];
        __nv_bfloat16 hi = __float2bfloat16(v);
        g_W2Thi[idx] = hi;
        g_W2Tlo[idx] = __float2bfloat16(v - __bfloat162float(hi));
        if (k == 0) g_b2p[q] = b2[i * 64 + j];
    } else {
        int idx = (b - 26024) * 256 + tid;
        if (idx < 64 * 192) {
            int k = idx / 192, col = idx % 192;
            g_WihT[idx] = Wih[(size_t)col * 64 + k];
            g_WhhT[idx] = Whh[(size_t)col * 64 + k];
        }
    }
}

// ---------------- ew GEMM via mma.sync (bf16 split, K'=192 concat) ----------------
// CTA: 128e x 128q, 4 warps of 64x64. K resident in smem (3-seg, measured-good layout).
// NEW: smem-staged coalesced epilogue (128B stores).
#define APAD 200
#define SROWB 400   // bytes per smem row

__global__ void __launch_bounds__(128, 2) ew_gemm_mma_kernel() {
    extern __shared__ __nv_bfloat16 dsm[];
    __nv_bfloat16* sA = dsm;                 // 128 x APAD
    __nv_bfloat16* sB = dsm + 128 * APAD;    // 128 x APAD
    __shared__ float sbias[128];

    int tid = threadIdx.x;
    int q0 = blockIdx.x * 128;
    int e0 = blockIdx.y * 128;

    sbias[tid] = g_b2p[q0 + tid];

    // load A' and B' tiles (seg 0: hi/hi, 1: hi/lo, 2: lo/hi)
#pragma unroll
    for (int seg = 0; seg < 3; seg++) {
        const __nv_bfloat16* asrc = (seg == 2) ? g_tlo : g_thi;
        const __nv_bfloat16* bsrc = (seg == 1) ? g_W2Tlo : g_W2Thi;
#pragma unroll
        for (int i = 0; i < 8; i++) {
            int flat = i * 128 + tid;        // 0..1023
            int row = flat >> 3, u = flat & 7;
            int e = e0 + row;
            uint4 av = make_uint4(0u, 0u, 0u, 0u);
            if (e < EE) av = *(const uint4*)&asrc[(size_t)e * 64 + u * 8];
            *(uint4*)((char*)sA + row * SROWB + seg * 128 + u * 16) = av;
            uint4 bv = *(const uint4*)&bsrc[(size_t)(q0 + row) * 64 + u * 8];
            *(uint4*)((char*)sB + row * SROWB + seg * 128 + u * 16) = bv;
        }
    }
    __syncthreads();

    int warp = tid >> 5, lane = tid & 31;
    int wm = (warp & 1) * 64;    // edge-row offset of warp tile
    int wn = (warp >> 1) * 64;   // q-col offset of warp tile

    float acc[4][8][4];
#pragma unroll
    for (int a = 0; a < 4; a++)
#pragma unroll
        for (int b = 0; b < 8; b++)
#pragma unroll
            for (int c = 0; c < 4; c++) acc[a][b][c] = 0.0f;

    uint32_t sA32 = smem_u32(sA);
    uint32_t sB32 = smem_u32(sB);

    int alr = ((lane >> 3) & 1) * 8 + (lane & 7);
    int alc = (lane >> 4) * 8;
    uint32_t aBase = sA32 + (wm + alr) * SROWB + alc * 2;

    int bg = lane >> 3;
    int blr = ((bg >> 1) * 8) + (lane & 7);
    int blc = (bg & 1) * 8;
    uint32_t bBase = sB32 + (wn + blr) * SROWB + blc * 2;

#pragma unroll
    for (int ks = 0; ks < 12; ks++) {
        uint32_t koff = ks * 32;
        uint32_t a[4][4], bf[4][4];
#pragma unroll
        for (int mt = 0; mt < 4; mt++) {
            asm volatile("ldmatrix.sync.aligned.m8n8.x4.shared.b16 {%0,%1,%2,%3}, [%4];"
                         : "=r"(a[mt][0]), "=r"(a[mt][1]), "=r"(a[mt][2]), "=r"(a[mt][3])
                         : "r"(aBase + mt * 16 * SROWB + koff));
        }
#pragma unroll
        for (int g = 0; g < 4; g++) {
            asm volatile("ldmatrix.sync.aligned.m8n8.x4.shared.b16 {%0,%1,%2,%3}, [%4];"
                         : "=r"(bf[g][0]), "=r"(bf[g][1]), "=r"(bf[g][2]), "=r"(bf[g][3])
                         : "r"(bBase + g * 16 * SROWB + koff));
        }
#pragma unroll
        for (int mt = 0; mt < 4; mt++) {
#pragma unroll
            for (int g = 0; g < 4; g++) {
#pragma unroll
                for (int h = 0; h < 2; h++) {
                    int nt = g * 2 + h;
                    asm volatile(
                        "mma.sync.aligned.m16n8k16.row.col.f32.bf16.bf16.f32 "
                        "{%0,%1,%2,%3}, {%4,%5,%6,%7}, {%8,%9}, {%0,%1,%2,%3};"
                        : "+f"(acc[mt][nt][0]), "+f"(acc[mt][nt][1]),
                          "+f"(acc[mt][nt][2]), "+f"(acc[mt][nt][3])
                        : "r"(a[mt][0]), "r"(a[mt][1]), "r"(a[mt][2]), "r"(a[mt][3]),
                          "r"(bf[g][h * 2]), "r"(bf[g][h * 2 + 1]));
                }
            }
        }
    }

    // ---- epilogue v2: stage bf16 pairs in smem [128][68] u32, then 128B stores ----
    __syncthreads();                         // A/B reads done; reuse dsm
    uint32_t* Cs = (uint32_t*)dsm;           // 128 x 68 u32 = 34816B (< 100KB dyn smem)
#pragma unroll
    for (int mt = 0; mt < 4; mt++) {
        int r0 = wm + mt * 16 + (lane >> 2); // local edge row (0..127)
#pragma unroll
        for (int nt = 0; nt < 8; nt++) {
            int qrel = wn + nt * 8 + (lane & 3) * 2;
            int p = qrel >> 1;               // local pair index 0..63
            float bx = sbias[qrel], by = sbias[qrel + 1];
            Cs[r0 * 68 + p]       = pack_bf2(acc[mt][nt][0] + bx, acc[mt][nt][1] + by);
            Cs[(r0 + 8) * 68 + p] = pack_bf2(acc[mt][nt][2] + bx, acc[mt][nt][3] + by);
        }
    }
    __syncthreads();
    // copy: 256 chunks of 128B (row 0..127 x jj 0..1), 1 chunk per warp-iteration
    int j0 = q0 >> 6;
    uint32_t* ewu = (uint32_t*)g_ewb;
    for (int it = warp; it < 256; it += 4) {
        int row = it >> 1, jj = it & 1;
        int e = e0 + row;
        if (e < EE) {
            uint32_t v = Cs[row * 68 + jj * 32 + lane];
            ewu[(size_t)e * 2048 + (size_t)(j0 + jj) * 32 + lane] = v;
        }
    }
}

// ---------------- zero kernel ----------------
__global__ void zero_gsum_kernel() {
    int i = blockIdx.x * blockDim.x + threadIdx.x;
    if (i < GG * 64) g_gsum[i] = 0.0f;
}

// ---------------- per-edge matvec + scatter: 1 warp per edge, bf16 pairs -------------
__global__ void msg_kernel(const int* __restrict__ ei) {
    __shared__ float hs[8][64];
    int w = threadIdx.x >> 5, lane = threadIdx.x & 31;
    int e = blockIdx.x * 8 + w;
    int s = ei[e];
    hs[w][lane]      = g_h[(size_t)s * 64 + lane];
    hs[w][lane + 32] = g_h[(size_t)s * 64 + 32 + lane];
    __syncwarp();
    const __nv_bfloat162* row = &g_ewb[(size_t)e * 2048 + lane];
    const float* hb = hs[w];
    float acc0 = 0.0f, acc1 = 0.0f;
#pragma unroll
    for (int j = 0; j < 64; j++) {
        __nv_bfloat162 v = __ldcs(&row[(size_t)j * 32]);
        float hj = hb[j];
        acc0 = fmaf(__bfloat162float(v.x), hj, acc0);
        acc1 = fmaf(__bfloat162float(v.y), hj, acc1);
    }
    int d = ei[EE + e];
    float* dst = &g_magg[(size_t)d * 64 + 2 * lane];
    atomicAdd(dst, acc0);
    atomicAdd(dst + 1, acc1);
}

// ---------------- GRU cell: transposed weights, 4 nodes/thread, re-zeroes magg -------
__global__ void __launch_bounds__(256) gru_kernel(const float* __restrict__ bih,
                                                  const float* __restrict__ bhh) {
    __shared__ float sm[16][64], sh[16][64];
    int n0 = blockIdx.x * 16;
    int tid = threadIdx.x;
#pragma unroll
    for (int i = 0; i < 4; i++) {
        int f = i * 256 + tid;
        int nn = f >> 6, c = f & 63;
        sm[nn][c] = g_magg[(size_t)(n0 + nn) * 64 + c];
        sh[nn][c] = g_h[(size_t)(n0 + nn) * 64 + c];
    }
    __syncthreads();
#pragma unroll
    for (int i = 0; i < 4; i++) {
        int f = i * 256 + tid;
        int nn = f >> 6, c = f & 63;
        g_magg[(size_t)(n0 + nn) * 64 + c] = 0.0f;
    }
    int slot = tid >> 6, c = tid & 63;
    float bir = bih[c], biz = bih[c + 64], bin = bih[c + 128];
    float bhr = bhh[c], bhz = bhh[c + 64], bhn = bhh[c + 128];
    float gir[4], giz[4], gin[4], ghr[4], ghz[4], ghn[4];
#pragma unroll
    for (int u = 0; u < 4; u++) {
        gir[u] = bir; giz[u] = biz; gin[u] = bin;
        ghr[u] = bhr; ghz[u] = bhz; ghn[u] = bhn;
    }
    const float* mrow0 = &sm[slot * 4][0];
    const float* hrow0 = &sh[slot * 4][0];
#pragma unroll 8
    for (int k = 0; k < 64; k++) {
        float wr = g_WihT[k * 192 + c];
        float wz = g_WihT[k * 192 + 64 + c];
        float wn = g_WihT[k * 192 + 128 + c];
        float vr = g_WhhT[k * 192 + c];
        float vz = g_WhhT[k * 192 + 64 + c];
        float vn = g_WhhT[k * 192 + 128 + c];
#pragma unroll
        for (int u = 0; u < 4; u++) {
            float mk = mrow0[u * 64 + k];
            float hk = hrow0[u * 64 + k];
            gir[u] = fmaf(mk, wr, gir[u]);
            giz[u] = fmaf(mk, wz, giz[u]);
            gin[u] = fmaf(mk, wn, gin[u]);
            ghr[u] = fmaf(hk, vr, ghr[u]);
            ghz[u] = fmaf(hk, vz, ghz[u]);
            ghn[u] = fmaf(hk, vn, ghn[u]);
        }
    }
#pragma unroll
    for (int u = 0; u < 4; u++) {
        float r = sigm(gir[u] + ghr[u]);
        float z = sigm(giz[u] + ghz[u]);
        float nv = tanhf(gin[u] + r * ghn[u]);
        int n = n0 + slot * 4 + u;
        g_h[(size_t)n * 64 + c] = (1.0f - z) * nv + z * hrow0[u * 64 + c];
    }
}

// ---------------- graph readout scatter ----------------
__global__ void rsum_kernel(const int* __restrict__ batch) {
    int idx = blockIdx.x * blockDim.x + threadIdx.x;
    if (idx >= NN * 64) return;
    int n = idx >> 6, c = idx & 63;
    atomicAdd(&g_gsum[batch[n] * 64 + c], g_h[idx]);
}

// ---------------- final MLP: relu(g@W_r1+b_r1)@W_r2+b_r2 ----------------
__global__ void final_kernel(const float* __restrict__ Wr1, const float* __restrict__ br1,
                             const float* __restrict__ Wr2, const float* __restrict__ br2,
                             float* __restrict__ out) {
    __shared__ float sg[64], sr[64];
    int g = blockIdx.x;
    int c = threadIdx.x;
    sg[c] = g_gsum[g * 64 + c];
    __syncthreads();
    float acc = br1[c];
#pragma unroll
    for (int k = 0; k < 64; k++) acc = fmaf(sg[k], Wr1[k * 64 + c], acc);
    sr[c] = fmaxf(acc, 0.0f);
    __syncthreads();
    if (c < OUTD) {
        float o = br2[c];
#pragma unroll
        for (int k = 0; k < 64; k++) o = fmaf(sr[k], Wr2[k * 32 + c], o);
        out[g * OUTD + c] = o;
    }
}

// ---------------- launch ----------------
extern "C" void kernel_launch(void* const* d_in, const int* in_sizes, int n_in,
                              void* d_out, int out_size) {
    const float* x    = (const float*)d_in[0];
    const int*   ei   = (const int*)d_in[1];
    const float* ea   = (const float*)d_in[2];
    const int*   batch= (const int*)d_in[3];
    const float* Wenc = (const float*)d_in[4];
    const float* benc = (const float*)d_in[5];
    const float* We1  = (const float*)d_in[6];
    const float* be1  = (const float*)d_in[7];
    const float* We2  = (const float*)d_in[8];
    const float* be2  = (const float*)d_in[9];
    const float* Wih  = (const float*)d_in[10];
    const float* Whh  = (const float*)d_in[11];
    const float* bih  = (const float*)d_in[12];
    const float* bhh  = (const float*)d_in[13];
    const float* Wr1  = (const float*)d_in[14];
    const float* br1  = (const float*)d_in[15];
    const float* Wr2  = (const float*)d_in[16];
    const float* br2  = (const float*)d_in[17];
    float* out = (float*)d_out;

    const int gemm_smem = 2 * 128 * APAD * (int)sizeof(__nv_bfloat16);  // 102400
    cudaFuncSetAttribute(ew_gemm_mma_kernel,
                         cudaFuncAttributeMaxDynamicSharedMemorySize, gemm_smem);

    // Slot order: enc(1), edge_prep(2), zero_gsum(3), gemm(4) <- ncu captures #4.
    enc_kernel<<<NN / 16, 256>>>(x, Wenc, benc);
    edge_prep_kernel<<<25000 + 1024 + 48, 256>>>(ea, be1, We1, We2, be2, Wih, Whh);
    zero_gsum_kernel<<<16, 256>>>();
    ew_gemm_mma_kernel<<<dim3(32, (EE + 127) / 128), 128, gemm_smem>>>();

    for (int s = 0; s < 3; s++) {
        msg_kernel<<<EE / 8, 256>>>(ei);
        gru_kernel<<<NN / 16, 256>>>(bih, bhh);
    }

    rsum_kernel<<<(NN * 64 + 255) / 256, 256>>>(batch);
    final_kernel<<<GG, 64>>>(Wr1, br1, Wr2, br2, out);
}

// round 17
// speedup vs baseline: 1.5078x; 1.0071x over previous
#include <cuda_runtime.h>
#include <cuda_bf16.h>
#include <math.h>
#include <stdint.h>

#define NN 50000
#define EE 100000
#define HH 64
#define GG 64
#define OUTD 32

// ---------------- device scratch (static globals; no runtime allocation) ---------------
__device__ float g_h[(size_t)NN * HH];          // node state
__device__ float g_magg[(size_t)NN * HH];       // aggregated messages
__device__ float g_b2p[4096];                   // column-permuted b_e2
__device__ float g_WihT[64 * 192];              // GRU input weights transposed [k][3H]
__device__ float g_WhhT[64 * 192];              // GRU hidden weights transposed [k][3H]
__device__ float g_gsum[GG * HH];               // per-graph sums
// ew in bf16 pairs: g_ewb[e][j][i/2] = (ew[e,i,j], ew[e,i+1,j])
__device__ __nv_bfloat162 g_ewb[(size_t)EE * 2048];
// bf16-split, permuted+transposed W_e2: rows q (0..4095), cols k (0..63)
__device__ __nv_bfloat16 g_W2Thi[(size_t)4096 * 64];
__device__ __nv_bfloat16 g_W2Tlo[(size_t)4096 * 64];
// bf16-split edge hidden t: [e][k]
__device__ __nv_bfloat16 g_thi[(size_t)EE * 64];
__device__ __nv_bfloat16 g_tlo[(size_t)EE * 64];

// ---------------- small helpers ----------------
__device__ __forceinline__ float sigm(float x) { return 1.0f / (1.0f + expf(-x)); }

__device__ __forceinline__ uint32_t smem_u32(const void* p) {
    uint32_t a;
    asm("{ .reg .u64 t; cvta.to.shared.u64 t, %1; cvt.u32.u64 %0, t; }" : "=r"(a) : "l"(p));
    return a;
}

__device__ __forceinline__ uint32_t pack_bf2(float a, float b) {
    __nv_bfloat162 t;
    t.x = __float2bfloat16(a);
    t.y = __float2bfloat16(b);
    return *(uint32_t*)&t;
}

__device__ __forceinline__ void cp_async16(uint32_t dst, const void* src, uint32_t src_sz) {
    asm volatile("cp.async.cg.shared.global [%0], [%1], 16, %2;"
                 :: "r"(dst), "l"(src), "r"(src_sz));
}

// ---------------- node encoder (self-contained): h = x@W_enc + b, magg = 0 ----------
__global__ void __launch_bounds__(256) enc_kernel(const float* __restrict__ x,
                                                  const float* __restrict__ Wenc,
                                                  const float* __restrict__ benc) {
    __shared__ float sx[16][128];
    int n0 = blockIdx.x * 16;
    int tid = threadIdx.x;
#pragma unroll
    for (int i = 0; i < 2; i++) {
        int f = i * 256 + tid;
        int row = f >> 5, q4 = (f & 31) * 4;
        *(float4*)&sx[row][q4] = *(const float4*)&x[(size_t)(n0 + row) * 128 + q4];
    }
    __syncthreads();
    int slot = tid >> 6, c = tid & 63;
    float b = benc[c];
    float acc[4] = {b, b, b, b};
    const float* xr = &sx[slot * 4][0];
#pragma unroll 8
    for (int k = 0; k < 128; k++) {
        float w = Wenc[k * 64 + c];
#pragma unroll
        for (int u = 0; u < 4; u++)
            acc[u] = fmaf(xr[u * 128 + k], w, acc[u]);
    }
#pragma unroll
    for (int u = 0; u < 4; u++) {
        int n = n0 + slot * 4 + u;
        g_h[(size_t)n * 64 + c] = acc[u];
        g_magg[(size_t)n * 64 + c] = 0.0f;
    }
}

// ---------------- edge_prep: edge_t + splitW2 + GRU weight transpose (grid-branched) --
__global__ void __launch_bounds__(256) edge_prep_kernel(
    const float* __restrict__ ea, const float* __restrict__ be1,
    const float* __restrict__ W1,
    const float* __restrict__ W2, const float* __restrict__ b2,
    const float* __restrict__ Wih, const float* __restrict__ Whh) {
    int b = blockIdx.x;
    int tid = threadIdx.x;
    if (b < 25000) {
        __shared__ float sW1[1024];
        __shared__ float sea[4][16];
        __shared__ float sbe[64];
        int e0 = b * 4;
#pragma unroll
        for (int i = 0; i < 4; i++) sW1[i * 256 + tid] = W1[i * 256 + tid];
        if (tid < 64) {
            sea[tid >> 4][tid & 15] = ea[(size_t)e0 * 16 + tid];
            sbe[tid] = be1[tid];
        }
        __syncthreads();
        int le = tid >> 6, c = tid & 63;
        int e = e0 + le;
        float acc = sbe[c];
#pragma unroll
        for (int k = 0; k < 16; k++)
            acc = fmaf(sea[le][k], sW1[k * 64 + c], acc);
        float v = fmaxf(acc, 0.0f);
        __nv_bfloat16 hi = __float2bfloat16(v);
        size_t idx = (size_t)e * 64 + c;
        g_thi[idx] = hi;
        g_tlo[idx] = __float2bfloat16(v - __bfloat162float(hi));
    } else if (b < 26024) {
        int idx = (b - 25000) * 256 + tid;
        int q = idx >> 6, k = idx & 63;
        int i = q & 63, j = q >> 6;
        float v = W2[(size_t)k * 4096 + i * 64 + j];
        __nv_bfloat16 hi = __float2bfloat16(v);
        g_W2Thi[idx] = hi;
        g_W2Tlo[idx] = __float2bfloat16(v - __bfloat162float(hi));
        if (k == 0) g_b2p[q] = b2[i * 64 + j];
    } else {
        int idx = (b - 26024) * 256 + tid;
        if (idx < 64 * 192) {
            int k = idx / 192, col = idx % 192;
            g_WihT[idx] = Wih[(size_t)col * 64 + k];
            g_WhhT[idx] = Whh[(size_t)col * 64 + k];
        }
    }
}

// ---------------- ew GEMM via mma.sync (bf16 split, K'=192 concat) ----------------
// CTA: 128e x 128q, 4 warps of 64x64 (measured-good layout).
// NEW: cp.async group-per-pass prologue — segment s loads overlap pass s-1 compute.
#define APAD 200
#define SROWB 400   // bytes per smem row

__global__ void __launch_bounds__(128, 2) ew_gemm_mma_kernel() {
    extern __shared__ __nv_bfloat16 dsm[];
    __nv_bfloat16* sA = dsm;                 // 128 x APAD
    __nv_bfloat16* sB = dsm + 128 * APAD;    // 128 x APAD
    __shared__ float sbias[128];

    int tid = threadIdx.x;
    int q0 = blockIdx.x * 128;
    int e0 = blockIdx.y * 128;

    uint32_t sA32 = smem_u32(sA);
    uint32_t sB32 = smem_u32(sB);

    // ---- issue all three segment loads as cp.async groups (seg 0,1,2) ----
#pragma unroll
    for (int seg = 0; seg < 3; seg++) {
        const __nv_bfloat16* asrc = (seg == 2) ? g_tlo : g_thi;
        const __nv_bfloat16* bsrc = (seg == 1) ? g_W2Tlo : g_W2Thi;
#pragma unroll
        for (int i = 0; i < 8; i++) {
            int flat = i * 128 + tid;        // 0..1023
            int row = flat >> 3, u = flat & 7;
            int e = e0 + row;
            size_t es = (e < EE) ? (size_t)e : 0;
            uint32_t asz = (e < EE) ? 16u : 0u;
            cp_async16(sA32 + row * SROWB + seg * 128 + u * 16,
                       &asrc[es * 64 + u * 8], asz);
            cp_async16(sB32 + row * SROWB + seg * 128 + u * 16,
                       &bsrc[(size_t)(q0 + row) * 64 + u * 8], 16u);
        }
        asm volatile("cp.async.commit_group;");
    }

    sbias[tid] = g_b2p[q0 + tid];

    int warp = tid >> 5, lane = tid & 31;
    int wm = (warp & 1) * 64;    // edge-row offset of warp tile
    int wn = (warp >> 1) * 64;   // q-col offset of warp tile

    float acc[4][8][4];
#pragma unroll
    for (int a = 0; a < 4; a++)
#pragma unroll
        for (int b = 0; b < 8; b++)
#pragma unroll
            for (int c = 0; c < 4; c++) acc[a][b][c] = 0.0f;

    int alr = ((lane >> 3) & 1) * 8 + (lane & 7);
    int alc = (lane >> 4) * 8;
    uint32_t aBase = sA32 + (wm + alr) * SROWB + alc * 2;

    int bg = lane >> 3;
    int blr = ((bg >> 1) * 8) + (lane & 7);
    int blc = (bg & 1) * 8;
    uint32_t bBase = sB32 + (wn + blr) * SROWB + blc * 2;

    auto run_pass = [&](int base) {
#pragma unroll
        for (int kk = 0; kk < 4; kk++) {
            uint32_t koff = base + kk * 32;
            uint32_t a[4][4], bf[4][4];
#pragma unroll
            for (int mt = 0; mt < 4; mt++) {
                asm volatile("ldmatrix.sync.aligned.m8n8.x4.shared.b16 {%0,%1,%2,%3}, [%4];"
                             : "=r"(a[mt][0]), "=r"(a[mt][1]), "=r"(a[mt][2]), "=r"(a[mt][3])
                             : "r"(aBase + mt * 16 * SROWB + koff));
            }
#pragma unroll
            for (int g = 0; g < 4; g++) {
                asm volatile("ldmatrix.sync.aligned.m8n8.x4.shared.b16 {%0,%1,%2,%3}, [%4];"
                             : "=r"(bf[g][0]), "=r"(bf[g][1]), "=r"(bf[g][2]), "=r"(bf[g][3])
                             : "r"(bBase + g * 16 * SROWB + koff));
            }
#pragma unroll
            for (int mt = 0; mt < 4; mt++) {
#pragma unroll
                for (int g = 0; g < 4; g++) {
#pragma unroll
                    for (int h = 0; h < 2; h++) {
                        int nt = g * 2 + h;
                        asm volatile(
                            "mma.sync.aligned.m16n8k16.row.col.f32.bf16.bf16.f32 "
                            "{%0,%1,%2,%3}, {%4,%5,%6,%7}, {%8,%9}, {%0,%1,%2,%3};"
                            : "+f"(acc[mt][nt][0]), "+f"(acc[mt][nt][1]),
                              "+f"(acc[mt][nt][2]), "+f"(acc[mt][nt][3])
                            : "r"(a[mt][0]), "r"(a[mt][1]), "r"(a[mt][2]), "r"(a[mt][3]),
                              "r"(bf[g][h * 2]), "r"(bf[g][h * 2 + 1]));
                    }
                }
            }
        }
    };

    // pass 0: wait seg 0 only (segs 1,2 still in flight)
    asm volatile("cp.async.wait_group 2;");
    __syncthreads();
    run_pass(0);
    // pass 1: wait seg 1
    asm volatile("cp.async.wait_group 1;");
    __syncthreads();
    run_pass(128);
    // pass 2: wait seg 2
    asm volatile("cp.async.wait_group 0;");
    __syncthreads();
    run_pass(256);

    // ---- epilogue: stage bf16 pairs in smem [128][68] u32, then 128B stores ----
    __syncthreads();                         // A/B reads done; reuse dsm
    uint32_t* Cs = (uint32_t*)dsm;           // 128 x 68 u32
#pragma unroll
    for (int mt = 0; mt < 4; mt++) {
        int r0 = wm + mt * 16 + (lane >> 2);
#pragma unroll
        for (int nt = 0; nt < 8; nt++) {
            int qrel = wn + nt * 8 + (lane & 3) * 2;
            int p = qrel >> 1;
            float bx = sbias[qrel], by = sbias[qrel + 1];
            Cs[r0 * 68 + p]       = pack_bf2(acc[mt][nt][0] + bx, acc[mt][nt][1] + by);
            Cs[(r0 + 8) * 68 + p] = pack_bf2(acc[mt][nt][2] + bx, acc[mt][nt][3] + by);
        }
    }
    __syncthreads();
    int j0 = q0 >> 6;
    uint32_t* ewu = (uint32_t*)g_ewb;
    for (int it = warp; it < 256; it += 4) {
        int row = it >> 1, jj = it & 1;
        int e = e0 + row;
        if (e < EE) {
            uint32_t v = Cs[row * 68 + jj * 32 + lane];
            ewu[(size_t)e * 2048 + (size_t)(j0 + jj) * 32 + lane] = v;
        }
    }
}

// ---------------- zero kernel ----------------
__global__ void zero_gsum_kernel() {
    int i = blockIdx.x * blockDim.x + threadIdx.x;
    if (i < GG * 64) g_gsum[i] = 0.0f;
}

// ---------------- per-edge matvec + scatter: 1 warp per edge, bf16 pairs -------------
__global__ void msg_kernel(const int* __restrict__ ei) {
    __shared__ float hs[8][64];
    int w = threadIdx.x >> 5, lane = threadIdx.x & 31;
    int e = blockIdx.x * 8 + w;
    int s = ei[e];
    hs[w][lane]      = g_h[(size_t)s * 64 + lane];
    hs[w][lane + 32] = g_h[(size_t)s * 64 + 32 + lane];
    __syncwarp();
    const __nv_bfloat162* row = &g_ewb[(size_t)e * 2048 + lane];
    const float* hb = hs[w];
    float acc0 = 0.0f, acc1 = 0.0f;
#pragma unroll
    for (int j = 0; j < 64; j++) {
        __nv_bfloat162 v = __ldcs(&row[(size_t)j * 32]);
        float hj = hb[j];
        acc0 = fmaf(__bfloat162float(v.x), hj, acc0);
        acc1 = fmaf(__bfloat162float(v.y), hj, acc1);
    }
    int d = ei[EE + e];
    float* dst = &g_magg[(size_t)d * 64 + 2 * lane];
    atomicAdd(dst, acc0);
    atomicAdd(dst + 1, acc1);
}

// ---------------- GRU cell: transposed weights, 4 nodes/thread, re-zeroes magg -------
__global__ void __launch_bounds__(256) gru_kernel(const float* __restrict__ bih,
                                                  const float* __restrict__ bhh) {
    __shared__ float sm[16][64], sh[16][64];
    int n0 = blockIdx.x * 16;
    int tid = threadIdx.x;
#pragma unroll
    for (int i = 0; i < 4; i++) {
        int f = i * 256 + tid;
        int nn = f >> 6, c = f & 63;
        sm[nn][c] = g_magg[(size_t)(n0 + nn) * 64 + c];
        sh[nn][c] = g_h[(size_t)(n0 + nn) * 64 + c];
    }
    __syncthreads();
#pragma unroll
    for (int i = 0; i < 4; i++) {
        int f = i * 256 + tid;
        int nn = f >> 6, c = f & 63;
        g_magg[(size_t)(n0 + nn) * 64 + c] = 0.0f;
    }
    int slot = tid >> 6, c = tid & 63;
    float bir = bih[c], biz = bih[c + 64], bin = bih[c + 128];
    float bhr = bhh[c], bhz = bhh[c + 64], bhn = bhh[c + 128];
    float gir[4], giz[4], gin[4], ghr[4], ghz[4], ghn[4];
#pragma unroll
    for (int u = 0; u < 4; u++) {
        gir[u] = bir; giz[u] = biz; gin[u] = bin;
        ghr[u] = bhr; ghz[u] = bhz; ghn[u] = bhn;
    }
    const float* mrow0 = &sm[slot * 4][0];
    const float* hrow0 = &sh[slot * 4][0];
#pragma unroll 8
    for (int k = 0; k < 64; k++) {
        float wr = g_WihT[k * 192 + c];
        float wz = g_WihT[k * 192 + 64 + c];
        float wn = g_WihT[k * 192 + 128 + c];
        float vr = g_WhhT[k * 192 + c];
        float vz = g_WhhT[k * 192 + 64 + c];
        float vn = g_WhhT[k * 192 + 128 + c];
#pragma unroll
        for (int u = 0; u < 4; u++) {
            float mk = mrow0[u * 64 + k];
            float hk = hrow0[u * 64 + k];
            gir[u] = fmaf(mk, wr, gir[u]);
            giz[u] = fmaf(mk, wz, giz[u]);
            gin[u] = fmaf(mk, wn, gin[u]);
            ghr[u] = fmaf(hk, vr, ghr[u]);
            ghz[u] = fmaf(hk, vz, ghz[u]);
            ghn[u] = fmaf(hk, vn, ghn[u]);
        }
    }
#pragma unroll
    for (int u = 0; u < 4; u++) {
        float r = sigm(gir[u] + ghr[u]);
        float z = sigm(giz[u] + ghz[u]);
        float nv = tanhf(gin[u] + r * ghn[u]);
        int n = n0 + slot * 4 + u;
        g_h[(size_t)n * 64 + c] = (1.0f - z) * nv + z * hrow0[u * 64 + c];
    }
}

// ---------------- graph readout scatter ----------------
__global__ void rsum_kernel(const int* __restrict__ batch) {
    int idx = blockIdx.x * blockDim.x + threadIdx.x;
    if (idx >= NN * 64) return;
    int n = idx >> 6, c = idx & 63;
    atomicAdd(&g_gsum[batch[n] * 64 + c], g_h[idx]);
}

// ---------------- final MLP: relu(g@W_r1+b_r1)@W_r2+b_r2 ----------------
__global__ void final_kernel(const float* __restrict__ Wr1, const float* __restrict__ br1,
                             const float* __restrict__ Wr2, const float* __restrict__ br2,
                             float* __restrict__ out) {
    __shared__ float sg[64], sr[64];
    int g = blockIdx.x;
    int c = threadIdx.x;
    sg[c] = g_gsum[g * 64 + c];
    __syncthreads();
    float acc = br1[c];
#pragma unroll
    for (int k = 0; k < 64; k++) acc = fmaf(sg[k], Wr1[k * 64 + c], acc);
    sr[c] = fmaxf(acc, 0.0f);
    __syncthreads();
    if (c < OUTD) {
        float o = br2[c];
#pragma unroll
        for (int k = 0; k < 64; k++) o = fmaf(sr[k], Wr2[k * 32 + c], o);
        out[g * OUTD + c] = o;
    }
}

// ---------------- launch ----------------
extern "C" void kernel_launch(void* const* d_in, const int* in_sizes, int n_in,
                              void* d_out, int out_size) {
    const float* x    = (const float*)d_in[0];
    const int*   ei   = (const int*)d_in[1];
    const float* ea   = (const float*)d_in[2];
    const int*   batch= (const int*)d_in[3];
    const float* Wenc = (const float*)d_in[4];
    const float* benc = (const float*)d_in[5];
    const float* We1  = (const float*)d_in[6];
    const float* be1  = (const float*)d_in[7];
    const float* We2  = (const float*)d_in[8];
    const float* be2  = (const float*)d_in[9];
    const float* Wih  = (const float*)d_in[10];
    const float* Whh  = (const float*)d_in[11];
    const float* bih  = (const float*)d_in[12];
    const float* bhh  = (const float*)d_in[13];
    const float* Wr1  = (const float*)d_in[14];
    const float* br1  = (const float*)d_in[15];
    const float* Wr2  = (const float*)d_in[16];
    const float* br2  = (const float*)d_in[17];
    float* out = (float*)d_out;

    const int gemm_smem = 2 * 128 * APAD * (int)sizeof(__nv_bfloat16);  // 102400
    cudaFuncSetAttribute(ew_gemm_mma_kernel,
                         cudaFuncAttributeMaxDynamicSharedMemorySize, gemm_smem);

    // Slot order: enc(1), edge_prep(2), zero_gsum(3), gemm(4) <- ncu captures #4.
    enc_kernel<<<NN / 16, 256>>>(x, Wenc, benc);
    edge_prep_kernel<<<25000 + 1024 + 48, 256>>>(ea, be1, We1, We2, be2, Wih, Whh);
    zero_gsum_kernel<<<16, 256>>>();
    ew_gemm_mma_kernel<<<dim3(32, (EE + 127) / 128), 128, gemm_smem>>>();

    for (int s = 0; s < 3; s++) {
        msg_kernel<<<EE / 8, 256>>>(ei);
        gru_kernel<<<NN / 16, 256>>>(bih, bhh);
    }

    rsum_kernel<<<(NN * 64 + 255) / 256, 256>>>(batch);
    final_kernel<<<GG, 64>>>(Wr1, br1, Wr2, br2, out);
}